// round 15
// baseline (speedup 1.0000x reference)
#include <cuda_runtime.h>
#include <cuda_fp16.h>
#include <stdint.h>

#define M_DIM 4096
#define N_DIM 4096
#define K_DIM 1024
#define KC    512     // reference panel size (two sequential chains + RN add)

typedef unsigned long long ull;

__device__ float g_xA2[(size_t)K_DIM * M_DIM * 2];  // X dup-pairs [K][2M]
__device__ float g_wT[(size_t)K_DIM * N_DIM];       // W k-major [K][N]
__device__ float g_p[(size_t)M_DIM * N_DIM];        // phase-1 partials

// ---------------------------------------------------------------------------
// helpers
// ---------------------------------------------------------------------------
__device__ __forceinline__ uint32_t smem_u32(const void* p) {
    uint32_t a;
    asm("{ .reg .u64 t; cvta.to.shared.u64 t, %1; cvt.u32.u64 %0, t; }"
        : "=r"(a) : "l"(p));
    return a;
}
#define CP16(saddr, gptr) \
    asm volatile("cp.async.cg.shared.global [%0], [%1], 16;" \
                 :: "r"(saddr), "l"(gptr) : "memory")
#define CP_COMMIT() asm volatile("cp.async.commit_group;" ::: "memory")
#define CP_WAIT1()  asm volatile("cp.async.wait_group 1;" ::: "memory")

__device__ __forceinline__ void fma2(ull& d, ull a, ull b) {
    asm("fma.rn.f32x2 %0, %1, %2, %0;" : "+l"(d) : "l"(a), "l"(b));
}
__device__ __forceinline__ float lo2(ull v) {
    return __uint_as_float((unsigned int)(v & 0xffffffffull));
}
__device__ __forceinline__ float hi2(ull v) {
    return __uint_as_float((unsigned int)(v >> 32));
}

// ---------------------------------------------------------------------------
// Decode X: pulse[(m*K+k)*16] -> dup pair at g_xA2[k*8192 + 2m] (exact)
// ---------------------------------------------------------------------------
__global__ void decode_x_kernel(const float* __restrict__ pulse,
                                float* __restrict__ outA2) {
    int i = blockIdx.x * blockDim.x + threadIdx.x;   // i = k*4096 + m
    int m = i & 4095;
    int k = i >> 12;
    const float4* p4 =
        reinterpret_cast<const float4*>(pulse + ((size_t)m * K_DIM + k) * 16);
    float4 a = p4[0], b = p4[1], c = p4[2], d = p4[3];
    float p[16] = {a.x, a.y, a.z, a.w, b.x, b.y, b.z, b.w,
                   c.x, c.y, c.z, c.w, d.x, d.y, d.z, d.w};
    unsigned int bits = 0;
#pragma unroll
    for (int j = 0; j < 16; j++)
        bits |= ((unsigned int)(p[j] > 0.5f)) << (15 - j);
    float v = __half2float(__ushort_as_half((unsigned short)bits));
    *reinterpret_cast<float2*>(outA2 + ((size_t)k * 8192 + 2 * m)) =
        make_float2(v, v);
}

// Decode W: pulse[(n*K+k)*16] -> g_wT[k*4096 + n]
__global__ void decode_w_kernel(const float* __restrict__ pulse,
                                float* __restrict__ outT) {
    int i = blockIdx.x * blockDim.x + threadIdx.x;
    int n = i & 4095;
    int k = i >> 12;
    const float4* p4 =
        reinterpret_cast<const float4*>(pulse + ((size_t)n * K_DIM + k) * 16);
    float4 a = p4[0], b = p4[1], c = p4[2], d = p4[3];
    float p[16] = {a.x, a.y, a.z, a.w, b.x, b.y, b.z, b.w,
                   c.x, c.y, c.z, c.w, d.x, d.y, d.z, d.w};
    unsigned int bits = 0;
#pragma unroll
    for (int j = 0; j < 16; j++)
        bits |= ((unsigned int)(p[j] > 0.5f)) << (15 - j);
    outT[i] = __half2float(__ushort_as_half((unsigned short)bits));
}

// ---------------------------------------------------------------------------
// Half-K GEMM phase: 3-stage cp.async pipeline, pre-packed A (dup pairs),
// fragment double buffering, zero packing MOVs in inner loop.
// Per output: strict k-ascending fp32 RN chain over [koff, koff+KC)
// (FFMA2 = per-lane IEEE RN; pairing over adjacent n; chain order unchanged).
// BM=BN=128, TILE_K=16, 256 threads, 8x8 microtile.
// n map: n = n0 + tx*2 + e + 32*j (conflict-free LDS.64 B fragments).
// ---------------------------------------------------------------------------
#define TILE_K 16
#define NT (KC / TILE_K)                      // 32
#define A_STAGE_FLOATS (TILE_K * 256)         // 4096 (dup pairs)
#define B_STAGE_FLOATS (TILE_K * 128)         // 2048
#define NSTAGE 3
#define SMEM_BYTES (NSTAGE * (A_STAGE_FLOATS + B_STAGE_FLOATS) * 4)  // 73728

template <bool PHASE2>
__global__ __launch_bounds__(256, 2)
void gemm_phase_kernel(const float* __restrict__ AT2,  // [K][2M] dup
                       const float* __restrict__ BT,   // [K][N]
                       float* __restrict__ part,
                       float* __restrict__ out, int koff) {
    extern __shared__ float sm[];
    float* Asm = sm;                                   // [NSTAGE][16][256]
    float* Bsm = sm + NSTAGE * A_STAGE_FLOATS;         // [NSTAGE][16][128]

    const int tid = threadIdx.x;
    const int tx = tid & 15;
    const int ty = tid >> 4;
    const int m0 = blockIdx.y * 128;
    const int n0 = blockIdx.x * 128;

    // copy indexing
    // A tile: 16 rows x 64 chunks(16B) = 1024 chunks; 4/thread
    const int ar = tid >> 6;                 // base row 0..3 (q adds 4)
    const int ac = (tid & 63) * 4;           // float col within dup row
    // B tile: 16 rows x 32 chunks = 512; 2/thread
    const int br = tid >> 5;                 // base row 0..7 (q adds 8)
    const int bc = (tid & 31) * 4;

    const uint32_t sA = smem_u32(Asm);
    const uint32_t sB = smem_u32(Bsm);

    ull acc2[8][4];
#pragma unroll
    for (int i = 0; i < 8; i++)
#pragma unroll
        for (int j = 0; j < 4; j++) acc2[i][j] = 0ull;

#define ISSUE(T)                                                              \
    do {                                                                      \
        const int _st = (T) % NSTAGE;                                         \
        const size_t _k0 = (size_t)(koff + (T) * TILE_K);                     \
        _Pragma("unroll")                                                     \
        for (int q = 0; q < 4; q++) {                                         \
            const int _r = ar + q * 4;                                        \
            CP16(sA + (uint32_t)(_st * A_STAGE_FLOATS + _r * 256 + ac) * 4,   \
                 AT2 + (_k0 + _r) * (2 * M_DIM) + 2 * m0 + ac);               \
        }                                                                     \
        _Pragma("unroll")                                                     \
        for (int q = 0; q < 2; q++) {                                         \
            const int _r = br + q * 8;                                        \
            CP16(sB + (uint32_t)(_st * B_STAGE_FLOATS + _r * 128 + bc) * 4,   \
                 BT + (_k0 + _r) * N_DIM + n0 + bc);                          \
        }                                                                     \
        CP_COMMIT();                                                          \
    } while (0)

    ISSUE(0);
    ISSUE(1);

    for (int t = 0; t < NT; t++) {
        CP_WAIT1();          // tile t landed (one younger group in flight)
        __syncthreads();     // all copies of tile t visible; also orders
                             // compute(t-1) before ISSUE(t+2) reuse of stage
        if (t + 2 < NT) ISSUE(t + 2);
        else CP_COMMIT();

        const int st = t % NSTAGE;
        const float* as = Asm + st * A_STAGE_FLOATS;
        const float* bs = Bsm + st * B_STAGE_FLOATS;

        // fragment double buffers — A pre-packed dup pairs (LDS.128)
        ulonglong2 aq[2][4];
        ull bfr[2][4];
#pragma unroll
        for (int ii = 0; ii < 4; ii++)
            aq[0][ii] = *reinterpret_cast<const ulonglong2*>(
                as + ty * 16 + ii * 4);
#pragma unroll
        for (int j = 0; j < 4; j++)
            bfr[0][j] = *reinterpret_cast<const ull*>(bs + tx * 2 + 32 * j);

#pragma unroll
        for (int k = 0; k < TILE_K; k++) {
            const int cur = k & 1, nxt = cur ^ 1;
            if (k + 1 < TILE_K) {
                const float* as1 = as + (k + 1) * 256;
                const float* bs1 = bs + (k + 1) * 128;
#pragma unroll
                for (int ii = 0; ii < 4; ii++)
                    aq[nxt][ii] = *reinterpret_cast<const ulonglong2*>(
                        as1 + ty * 16 + ii * 4);
#pragma unroll
                for (int j = 0; j < 4; j++)
                    bfr[nxt][j] = *reinterpret_cast<const ull*>(
                        bs1 + tx * 2 + 32 * j);
            }
            const ull ar2[8] = {aq[cur][0].x, aq[cur][0].y,
                                aq[cur][1].x, aq[cur][1].y,
                                aq[cur][2].x, aq[cur][2].y,
                                aq[cur][3].x, aq[cur][3].y};
#pragma unroll
            for (int i = 0; i < 8; i++)
#pragma unroll
                for (int j = 0; j < 4; j++)
                    fma2(acc2[i][j], ar2[i], bfr[cur][j]);
        }
    }
#undef ISSUE

    if (!PHASE2) {
#pragma unroll
        for (int i = 0; i < 8; i++) {
            const int m = m0 + ty * 8 + i;
            float* dst = part + (size_t)m * N_DIM + n0 + tx * 2;
#pragma unroll
            for (int j = 0; j < 4; j++) {
                float2 v = make_float2(lo2(acc2[i][j]), hi2(acc2[i][j]));
                *reinterpret_cast<float2*>(dst + 32 * j) = v;
            }
        }
    } else {
#pragma unroll
        for (int i = 0; i < 8; i++) {
            const int m = m0 + ty * 8 + i;
            const float* psrc = part + (size_t)m * N_DIM + n0 + tx * 2;
#pragma unroll
            for (int j = 0; j < 4; j++) {
                float2 pv = *reinterpret_cast<const float2*>(psrc + 32 * j);
                float rv[2] = {pv.x + lo2(acc2[i][j]),
                               pv.y + hi2(acc2[i][j])};
#pragma unroll
                for (int e = 0; e < 2; e++) {
                    const int n = n0 + tx * 2 + e + 32 * j;
                    unsigned int u = (unsigned int)
                        __half_as_ushort(__float2half_rn(rv[e]));
                    float4* dst = reinterpret_cast<float4*>(
                        out + ((size_t)m * N_DIM + n) * 16);
#pragma unroll
                    for (int q = 0; q < 4; q++) {
                        float4 o;
                        o.x = __uint_as_float(
                            (unsigned)(((int)(u << (16 + q * 4 + 0))) >> 31)
                            & 0x3F800000u);
                        o.y = __uint_as_float(
                            (unsigned)(((int)(u << (16 + q * 4 + 1))) >> 31)
                            & 0x3F800000u);
                        o.z = __uint_as_float(
                            (unsigned)(((int)(u << (16 + q * 4 + 2))) >> 31)
                            & 0x3F800000u);
                        o.w = __uint_as_float(
                            (unsigned)(((int)(u << (16 + q * 4 + 3))) >> 31)
                            & 0x3F800000u);
                        dst[q] = o;
                    }
                }
            }
        }
    }
}

// ---------------------------------------------------------------------------
extern "C" void kernel_launch(void* const* d_in, const int* in_sizes, int n_in,
                              void* d_out, int out_size) {
    const float* x_pulse = (const float*)d_in[0];
    const float* w_pulse = (const float*)d_in[1];
    float* out = (float*)d_out;

    float *gx = nullptr, *gw = nullptr, *gp = nullptr;
    cudaGetSymbolAddress((void**)&gx, g_xA2);
    cudaGetSymbolAddress((void**)&gw, g_wT);
    cudaGetSymbolAddress((void**)&gp, g_p);

    const int n_el = M_DIM * K_DIM;

    decode_x_kernel<<<n_el / 256, 256>>>(x_pulse, gx);
    decode_w_kernel<<<n_el / 256, 256>>>(w_pulse, gw);

    cudaFuncSetAttribute(gemm_phase_kernel<false>,
                         cudaFuncAttributeMaxDynamicSharedMemorySize,
                         SMEM_BYTES);
    cudaFuncSetAttribute(gemm_phase_kernel<true>,
                         cudaFuncAttributeMaxDynamicSharedMemorySize,
                         SMEM_BYTES);

    dim3 grid(N_DIM / 128, M_DIM / 128);  // 32 x 32
    gemm_phase_kernel<false><<<grid, 256, SMEM_BYTES>>>(gx, gw, gp, out, 0);
    gemm_phase_kernel<true><<<grid, 256, SMEM_BYTES>>>(gx, gw, gp, out, KC);
}

// round 16
// speedup vs baseline: 1.0482x; 1.0482x over previous
#include <cuda_runtime.h>
#include <cuda_fp16.h>
#include <stdint.h>

#define M_DIM 4096
#define N_DIM 4096
#define K_DIM 1024

typedef unsigned long long ull;

__device__ float g_xT[(size_t)K_DIM * M_DIM];  // decoded X, k-major [K][M]
__device__ float g_wT[(size_t)K_DIM * N_DIM];  // decoded W, k-major [K][N]

// ---------------------------------------------------------------------------
// helpers
// ---------------------------------------------------------------------------
__device__ __forceinline__ uint32_t smem_u32(const void* p) {
    uint32_t a;
    asm("{ .reg .u64 t; cvta.to.shared.u64 t, %1; cvt.u32.u64 %0, t; }"
        : "=r"(a) : "l"(p));
    return a;
}
#define CP16(saddr, gptr) \
    asm volatile("cp.async.cg.shared.global [%0], [%1], 16;" \
                 :: "r"(saddr), "l"(gptr) : "memory")
#define CP_COMMIT() asm volatile("cp.async.commit_group;" ::: "memory")
#define CP_WAIT1()  asm volatile("cp.async.wait_group 1;" ::: "memory")

__device__ __forceinline__ ull pack2(float x) {
    ull r;
    asm("mov.b64 %0, {%1, %1};" : "=l"(r) : "f"(x));
    return r;
}
__device__ __forceinline__ void fma2(ull& d, ull a, ull b) {
    asm("fma.rn.f32x2 %0, %1, %2, %0;" : "+l"(d) : "l"(a), "l"(b));
}
__device__ __forceinline__ float lo2(ull v) {
    return __uint_as_float((unsigned int)(v & 0xffffffffull));
}
__device__ __forceinline__ float hi2(ull v) {
    return __uint_as_float((unsigned int)(v >> 32));
}

// ---------------------------------------------------------------------------
// Decode + transpose: pulse[(m*K+k)*16] -> outT[k*4096 + m]  (exact values)
// ---------------------------------------------------------------------------
__global__ void decode_transpose_kernel(const float* __restrict__ pulse,
                                        float* __restrict__ outT) {
    int i = blockIdx.x * blockDim.x + threadIdx.x;   // i = k*4096 + m
    int m = i & 4095;
    int k = i >> 12;
    const float4* p4 =
        reinterpret_cast<const float4*>(pulse + ((size_t)m * K_DIM + k) * 16);
    float4 a = p4[0], b = p4[1], c = p4[2], d = p4[3];
    float p[16] = {a.x, a.y, a.z, a.w, b.x, b.y, b.z, b.w,
                   c.x, c.y, c.z, c.w, d.x, d.y, d.z, d.w};
    unsigned int bits = 0;
#pragma unroll
    for (int j = 0; j < 16; j++)
        bits |= ((unsigned int)(p[j] > 0.5f)) << (15 - j);
    outT[i] = __half2float(__ushort_as_half((unsigned short)bits));
}

// ---------------------------------------------------------------------------
// Fused full-K GEMM (R12 mainloop, unchanged): 3-stage cp.async pipeline,
// fragment double buffering. Panel split k<512 / k>=512 preserved by
// spilling panel-0 accumulators to smem at the boundary and combining with
// a single RN add at the end (bit-identical to the two-kernel version).
// BM=BN=128, TILE_K=16, 256 threads, 8x8 microtile.
// n map: n = n0 + tx*2 + e + 32*j.
// ---------------------------------------------------------------------------
#define TILE_K 16
#define NT (K_DIM / TILE_K)                 // 64
#define NT_HALF (NT / 2)                    // 32 = k=512 panel boundary
#define STAGE_FLOATS (TILE_K * 128)         // 2048
#define NSTAGE 3
#define PIPE_FLOATS (NSTAGE * STAGE_FLOATS * 2)       // 12288
#define SMEM_BYTES (PIPE_FLOATS * 4 + 256 * 32 * 8)   // 49152 + 65536 = 114688

__global__ __launch_bounds__(256, 2)
void gemm_fused_kernel(const float* __restrict__ AT,   // [K][M]
                       const float* __restrict__ BT,   // [K][N]
                       float* __restrict__ out) {
    extern __shared__ float sm[];
    float* Asm = sm;                               // [NSTAGE][16][128]
    float* Bsm = sm + NSTAGE * STAGE_FLOATS;
    ull* spill = reinterpret_cast<ull*>(sm + PIPE_FLOATS);  // [32][256]

    const int tid = threadIdx.x;
    const int tx = tid & 15;
    const int ty = tid >> 4;
    const int m0 = blockIdx.y * 128;
    const int n0 = blockIdx.x * 128;

    // copy indexing: tile = 16 rows x 32 chunks(16B); 512 chunks; 2/thread/op
    const int r0 = tid >> 5;                // row 0..7
    const int c0 = (tid & 31) * 4;
    const int r1 = r0 + 8;                  // row 8..15

    const uint32_t sA = smem_u32(Asm);
    const uint32_t sB = smem_u32(Bsm);

    ull acc2[8][4];
#pragma unroll
    for (int i = 0; i < 8; i++)
#pragma unroll
        for (int j = 0; j < 4; j++) acc2[i][j] = 0ull;

#define ISSUE(T)                                                              \
    do {                                                                      \
        const int _st = (T) % NSTAGE;                                         \
        const size_t _k0 = (size_t)((T) * TILE_K);                            \
        CP16(sA + (uint32_t)(_st * STAGE_FLOATS + r0 * 128 + c0) * 4,         \
             AT + (_k0 + r0) * M_DIM + m0 + c0);                              \
        CP16(sA + (uint32_t)(_st * STAGE_FLOATS + r1 * 128 + c0) * 4,         \
             AT + (_k0 + r1) * M_DIM + m0 + c0);                              \
        CP16(sB + (uint32_t)(_st * STAGE_FLOATS + r0 * 128 + c0) * 4,         \
             BT + (_k0 + r0) * N_DIM + n0 + c0);                              \
        CP16(sB + (uint32_t)(_st * STAGE_FLOATS + r1 * 128 + c0) * 4,         \
             BT + (_k0 + r1) * N_DIM + n0 + c0);                              \
        CP_COMMIT();                                                          \
    } while (0)

    ISSUE(0);
    ISSUE(1);

    for (int t = 0; t < NT; t++) {
        // panel boundary: stash panel-0 accumulators, restart chains at 0
        if (t == NT_HALF) {
#pragma unroll
            for (int i = 0; i < 8; i++)
#pragma unroll
                for (int j = 0; j < 4; j++) {
                    spill[(i * 4 + j) * 256 + tid] = acc2[i][j];
                    acc2[i][j] = 0ull;
                }
        }

        CP_WAIT1();          // tile t landed (one younger group in flight)
        __syncthreads();     // all copies of tile t visible; also orders
                             // compute(t-1) before ISSUE(t+2) stage reuse
        if (t + 2 < NT) ISSUE(t + 2);
        else CP_COMMIT();

        const int st = t % NSTAGE;
        const float* as = Asm + st * STAGE_FLOATS;
        const float* bs = Bsm + st * STAGE_FLOATS;

        // fragment double buffers
        float4 afA[2], afB[2];
        ull bfr[2][4];
        afA[0] = *reinterpret_cast<const float4*>(as + ty * 8);
        afB[0] = *reinterpret_cast<const float4*>(as + ty * 8 + 4);
#pragma unroll
        for (int j = 0; j < 4; j++)
            bfr[0][j] = *reinterpret_cast<const ull*>(bs + tx * 2 + 32 * j);

#pragma unroll
        for (int k = 0; k < TILE_K; k++) {
            const int cur = k & 1, nxt = cur ^ 1;
            if (k + 1 < TILE_K) {
                afA[nxt] = *reinterpret_cast<const float4*>(
                    as + (k + 1) * 128 + ty * 8);
                afB[nxt] = *reinterpret_cast<const float4*>(
                    as + (k + 1) * 128 + ty * 8 + 4);
#pragma unroll
                for (int j = 0; j < 4; j++)
                    bfr[nxt][j] = *reinterpret_cast<const ull*>(
                        bs + (k + 1) * 128 + tx * 2 + 32 * j);
            }
            ull ar2[8];
            ar2[0] = pack2(afA[cur].x); ar2[1] = pack2(afA[cur].y);
            ar2[2] = pack2(afA[cur].z); ar2[3] = pack2(afA[cur].w);
            ar2[4] = pack2(afB[cur].x); ar2[5] = pack2(afB[cur].y);
            ar2[6] = pack2(afB[cur].z); ar2[7] = pack2(afB[cur].w);
#pragma unroll
            for (int i = 0; i < 8; i++)
#pragma unroll
                for (int j = 0; j < 4; j++)
                    fma2(acc2[i][j], ar2[i], bfr[cur][j]);
        }
    }
#undef ISSUE

    // epilogue: combine panels (b0 + b1, single RN add), encode, store
#pragma unroll
    for (int i = 0; i < 8; i++) {
        const int m = m0 + ty * 8 + i;
#pragma unroll
        for (int j = 0; j < 4; j++) {
            const ull s = spill[(i * 4 + j) * 256 + tid];
            float rv[2] = {lo2(s) + lo2(acc2[i][j]),
                           hi2(s) + hi2(acc2[i][j])};
#pragma unroll
            for (int e = 0; e < 2; e++) {
                const int n = n0 + tx * 2 + e + 32 * j;
                unsigned int u = (unsigned int)
                    __half_as_ushort(__float2half_rn(rv[e]));
                float4* dst = reinterpret_cast<float4*>(
                    out + ((size_t)m * N_DIM + n) * 16);
#pragma unroll
                for (int q = 0; q < 4; q++) {
                    float4 o;
                    o.x = __uint_as_float(
                        (unsigned)(((int)(u << (16 + q * 4 + 0))) >> 31)
                        & 0x3F800000u);
                    o.y = __uint_as_float(
                        (unsigned)(((int)(u << (16 + q * 4 + 1))) >> 31)
                        & 0x3F800000u);
                    o.z = __uint_as_float(
                        (unsigned)(((int)(u << (16 + q * 4 + 2))) >> 31)
                        & 0x3F800000u);
                    o.w = __uint_as_float(
                        (unsigned)(((int)(u << (16 + q * 4 + 3))) >> 31)
                        & 0x3F800000u);
                    dst[q] = o;
                }
            }
        }
    }
}

// ---------------------------------------------------------------------------
extern "C" void kernel_launch(void* const* d_in, const int* in_sizes, int n_in,
                              void* d_out, int out_size) {
    const float* x_pulse = (const float*)d_in[0];
    const float* w_pulse = (const float*)d_in[1];
    float* out = (float*)d_out;

    float *gx = nullptr, *gw = nullptr;
    cudaGetSymbolAddress((void**)&gx, g_xT);
    cudaGetSymbolAddress((void**)&gw, g_wT);

    const int n_el = M_DIM * K_DIM;

    decode_transpose_kernel<<<n_el / 256, 256>>>(x_pulse, gx);
    decode_transpose_kernel<<<n_el / 256, 256>>>(w_pulse, gw);

    cudaFuncSetAttribute(gemm_fused_kernel,
                         cudaFuncAttributeMaxDynamicSharedMemorySize,
                         SMEM_BYTES);

    dim3 grid(N_DIM / 128, M_DIM / 128);  // 32 x 32
    gemm_fused_kernel<<<grid, 256, SMEM_BYTES>>>(gx, gw, out);
}

// round 17
// speedup vs baseline: 1.1817x; 1.1274x over previous
#include <cuda_runtime.h>
#include <cuda_fp16.h>
#include <stdint.h>

#define M_DIM 4096
#define N_DIM 4096
#define K_DIM 1024
#define KC    512     // reference panel size (two sequential chains + RN add)

typedef unsigned long long ull;

__device__ float g_xT[(size_t)K_DIM * M_DIM];  // decoded X, k-major [K][M]
__device__ float g_wT[(size_t)K_DIM * N_DIM];  // decoded W, k-major [K][N]
__device__ float g_p[(size_t)M_DIM * N_DIM];   // phase-1 partials (CTA-linear)

// ---------------------------------------------------------------------------
// helpers
// ---------------------------------------------------------------------------
__device__ __forceinline__ uint32_t smem_u32(const void* p) {
    uint32_t a;
    asm("{ .reg .u64 t; cvta.to.shared.u64 t, %1; cvt.u32.u64 %0, t; }"
        : "=r"(a) : "l"(p));
    return a;
}
#define CP16(saddr, gptr) \
    asm volatile("cp.async.cg.shared.global [%0], [%1], 16;" \
                 :: "r"(saddr), "l"(gptr) : "memory")
#define CP_COMMIT() asm volatile("cp.async.commit_group;" ::: "memory")
#define CP_WAIT1()  asm volatile("cp.async.wait_group 1;" ::: "memory")

__device__ __forceinline__ ull pack2(float x) {
    ull r;
    asm("mov.b64 %0, {%1, %1};" : "=l"(r) : "f"(x));
    return r;
}
__device__ __forceinline__ void fma2(ull& d, ull a, ull b) {
    asm("fma.rn.f32x2 %0, %1, %2, %0;" : "+l"(d) : "l"(a), "l"(b));
}
__device__ __forceinline__ float lo2(ull v) {
    return __uint_as_float((unsigned int)(v & 0xffffffffull));
}
__device__ __forceinline__ float hi2(ull v) {
    return __uint_as_float((unsigned int)(v >> 32));
}

// ---------------------------------------------------------------------------
// Fused decode of both inputs: pulse[(r*K+k)*16] -> outT[k*4096 + r]
// ---------------------------------------------------------------------------
__global__ void decode_both_kernel(const float* __restrict__ x_pulse,
                                   const float* __restrict__ w_pulse,
                                   float* __restrict__ xT,
                                   float* __restrict__ wT) {
    int gi = blockIdx.x * blockDim.x + threadIdx.x;
    const int half = M_DIM * K_DIM;
    const float* pulse = (gi < half) ? x_pulse : w_pulse;
    float* outT = (gi < half) ? xT : wT;
    int i = (gi < half) ? gi : gi - half;   // i = k*4096 + r
    int r = i & 4095;
    int k = i >> 12;
    const float4* p4 =
        reinterpret_cast<const float4*>(pulse + ((size_t)r * K_DIM + k) * 16);
    float4 a = p4[0], b = p4[1], c = p4[2], d = p4[3];
    float p[16] = {a.x, a.y, a.z, a.w, b.x, b.y, b.z, b.w,
                   c.x, c.y, c.z, c.w, d.x, d.y, d.z, d.w};
    unsigned int bits = 0;
#pragma unroll
    for (int j = 0; j < 16; j++)
        bits |= ((unsigned int)(p[j] > 0.5f)) << (15 - j);
    outT[i] = __half2float(__ushort_as_half((unsigned short)bits));
}

// ---------------------------------------------------------------------------
// Half-K GEMM phase (R12 mainloop, unchanged): 3-stage cp.async pipeline +
// fragment double buffering. Per output: strict k-ascending fp32 RN chain
// over [koff, koff+KC); FFMA2 = per-lane IEEE RN (pairs over adjacent n).
// NEW: CTA-linear coalesced partial layout, L2 prefetch of partials,
// streaming cache hints on partial/output traffic.
// BM=BN=128, TILE_K=16, 256 threads, 8x8 microtile.
// n map: n = n0 + tx*2 + e + 32*j.
// ---------------------------------------------------------------------------
#define TILE_K 16
#define NT (KC / TILE_K)                    // 32
#define STAGE_FLOATS (TILE_K * 128)         // 2048
#define NSTAGE 3
#define SMEM_BYTES (NSTAGE * STAGE_FLOATS * 2 * 4)  // 49152

template <bool PHASE2>
__global__ __launch_bounds__(256, 1)
void gemm_phase_kernel(const float* __restrict__ AT,   // [K][M]
                       const float* __restrict__ BT,   // [K][N]
                       float* __restrict__ part,
                       float* __restrict__ out, int koff) {
    extern __shared__ float sm[];
    float* Asm = sm;                               // [NSTAGE][16][128]
    float* Bsm = sm + NSTAGE * STAGE_FLOATS;

    const int tid = threadIdx.x;
    const int tx = tid & 15;
    const int ty = tid >> 4;
    const int m0 = blockIdx.y * 128;
    const int n0 = blockIdx.x * 128;

    // CTA-linear partial block: 16384 floats (64 outputs x 256 threads)
    float* pbase =
        part + (size_t)(blockIdx.y * gridDim.x + blockIdx.x) * 16384;

    // copy indexing: tile = 16 rows x 32 chunks(16B); 512 chunks; 2/thread/op
    const int r0 = tid >> 5;                // row 0..7
    const int c0 = (tid & 31) * 4;
    const int r1 = r0 + 8;                  // row 8..15

    const uint32_t sA = smem_u32(Asm);
    const uint32_t sB = smem_u32(Bsm);

    ull acc2[8][4];
#pragma unroll
    for (int i = 0; i < 8; i++)
#pragma unroll
        for (int j = 0; j < 4; j++) acc2[i][j] = 0ull;

#define ISSUE(T)                                                              \
    do {                                                                      \
        const int _st = (T) % NSTAGE;                                         \
        const size_t _k0 = (size_t)(koff + (T) * TILE_K);                     \
        CP16(sA + (uint32_t)(_st * STAGE_FLOATS + r0 * 128 + c0) * 4,         \
             AT + (_k0 + r0) * M_DIM + m0 + c0);                              \
        CP16(sA + (uint32_t)(_st * STAGE_FLOATS + r1 * 128 + c0) * 4,         \
             AT + (_k0 + r1) * M_DIM + m0 + c0);                              \
        CP16(sB + (uint32_t)(_st * STAGE_FLOATS + r0 * 128 + c0) * 4,         \
             BT + (_k0 + r0) * N_DIM + n0 + c0);                              \
        CP16(sB + (uint32_t)(_st * STAGE_FLOATS + r1 * 128 + c0) * 4,         \
             BT + (_k0 + r1) * N_DIM + n0 + c0);                              \
        CP_COMMIT();                                                          \
    } while (0)

    ISSUE(0);
    ISSUE(1);

    for (int t = 0; t < NT; t++) {
        // prefetch this thread-block's partials into L2 before the epilogue
        if (PHASE2 && t == NT - 2) {
#pragma unroll
            for (int s = 0; s < 32; s++)
                asm volatile("prefetch.global.L2 [%0];"
                             :: "l"(pbase + s * 512 + tid * 2) : "memory");
        }

        CP_WAIT1();          // tile t landed (one younger group in flight)
        __syncthreads();     // all copies of tile t visible; also orders
                             // compute(t-1) before ISSUE(t+2) stage reuse
        if (t + 2 < NT) ISSUE(t + 2);
        else CP_COMMIT();

        const int st = t % NSTAGE;
        const float* as = Asm + st * STAGE_FLOATS;
        const float* bs = Bsm + st * STAGE_FLOATS;

        // fragment double buffers
        float4 afA[2], afB[2];
        ull bfr[2][4];
        afA[0] = *reinterpret_cast<const float4*>(as + ty * 8);
        afB[0] = *reinterpret_cast<const float4*>(as + ty * 8 + 4);
#pragma unroll
        for (int j = 0; j < 4; j++)
            bfr[0][j] = *reinterpret_cast<const ull*>(bs + tx * 2 + 32 * j);

#pragma unroll
        for (int k = 0; k < TILE_K; k++) {
            const int cur = k & 1, nxt = cur ^ 1;
            if (k + 1 < TILE_K) {
                afA[nxt] = *reinterpret_cast<const float4*>(
                    as + (k + 1) * 128 + ty * 8);
                afB[nxt] = *reinterpret_cast<const float4*>(
                    as + (k + 1) * 128 + ty * 8 + 4);
#pragma unroll
                for (int j = 0; j < 4; j++)
                    bfr[nxt][j] = *reinterpret_cast<const ull*>(
                        bs + (k + 1) * 128 + tx * 2 + 32 * j);
            }
            ull ar2[8];
            ar2[0] = pack2(afA[cur].x); ar2[1] = pack2(afA[cur].y);
            ar2[2] = pack2(afA[cur].z); ar2[3] = pack2(afA[cur].w);
            ar2[4] = pack2(afB[cur].x); ar2[5] = pack2(afB[cur].y);
            ar2[6] = pack2(afB[cur].z); ar2[7] = pack2(afB[cur].w);
#pragma unroll
            for (int i = 0; i < 8; i++)
#pragma unroll
                for (int j = 0; j < 4; j++)
                    fma2(acc2[i][j], ar2[i], bfr[cur][j]);
        }
    }
#undef ISSUE

    if (!PHASE2) {
        // fully-coalesced streaming stash: idx-major, tid-minor
#pragma unroll
        for (int i = 0; i < 8; i++)
#pragma unroll
            for (int j = 0; j < 4; j++) {
                float2 v = make_float2(lo2(acc2[i][j]), hi2(acc2[i][j]));
                __stcs(reinterpret_cast<float2*>(pbase) + (i * 4 + j) * 256 +
                           tid,
                       v);
            }
    } else {
#pragma unroll
        for (int i = 0; i < 8; i++) {
            const int m = m0 + ty * 8 + i;
#pragma unroll
            for (int j = 0; j < 4; j++) {
                float2 pv = __ldcs(reinterpret_cast<const float2*>(pbase) +
                                   (i * 4 + j) * 256 + tid);
                float rv[2] = {pv.x + lo2(acc2[i][j]),
                               pv.y + hi2(acc2[i][j])};
#pragma unroll
                for (int e = 0; e < 2; e++) {
                    const int n = n0 + tx * 2 + e + 32 * j;
                    unsigned int u = (unsigned int)
                        __half_as_ushort(__float2half_rn(rv[e]));
                    float4* dst = reinterpret_cast<float4*>(
                        out + ((size_t)m * N_DIM + n) * 16);
#pragma unroll
                    for (int q = 0; q < 4; q++) {
                        float4 o;
                        o.x = __uint_as_float(
                            (unsigned)(((int)(u << (16 + q * 4 + 0))) >> 31)
                            & 0x3F800000u);
                        o.y = __uint_as_float(
                            (unsigned)(((int)(u << (16 + q * 4 + 1))) >> 31)
                            & 0x3F800000u);
                        o.z = __uint_as_float(
                            (unsigned)(((int)(u << (16 + q * 4 + 2))) >> 31)
                            & 0x3F800000u);
                        o.w = __uint_as_float(
                            (unsigned)(((int)(u << (16 + q * 4 + 3))) >> 31)
                            & 0x3F800000u);
                        __stcs(dst + q, o);
                    }
                }
            }
        }
    }
}

// ---------------------------------------------------------------------------
extern "C" void kernel_launch(void* const* d_in, const int* in_sizes, int n_in,
                              void* d_out, int out_size) {
    const float* x_pulse = (const float*)d_in[0];
    const float* w_pulse = (const float*)d_in[1];
    float* out = (float*)d_out;

    float *gx = nullptr, *gw = nullptr, *gp = nullptr;
    cudaGetSymbolAddress((void**)&gx, g_xT);
    cudaGetSymbolAddress((void**)&gw, g_wT);
    cudaGetSymbolAddress((void**)&gp, g_p);

    const int n_el = M_DIM * K_DIM;

    decode_both_kernel<<<2 * n_el / 256, 256>>>(x_pulse, w_pulse, gx, gw);

    cudaFuncSetAttribute(gemm_phase_kernel<false>,
                         cudaFuncAttributeMaxDynamicSharedMemorySize,
                         SMEM_BYTES);
    cudaFuncSetAttribute(gemm_phase_kernel<true>,
                         cudaFuncAttributeMaxDynamicSharedMemorySize,
                         SMEM_BYTES);

    dim3 grid(N_DIM / 128, M_DIM / 128);  // 32 x 32
    gemm_phase_kernel<false><<<grid, 256, SMEM_BYTES>>>(gx, gw, gp, out, 0);
    gemm_phase_kernel<true><<<grid, 256, SMEM_BYTES>>>(gx, gw, gp, out, KC);
}